// round 16
// baseline (speedup 1.0000x reference)
#include <cuda_runtime.h>
#include <cuda_bf16.h>
#include <math.h>
#include <stdint.h>

#define B_     2
#define S_     2048
#define DM     1024
#define H_     16
#define DK     64
#define INNER_ 1024
#define NREL   4095

// ---------------- device scratch ----------------
__device__ float    g_q[B_ * H_ * S_ * DK];      // fp32 [B,H,S,DK]
__device__ float    g_k[B_ * H_ * S_ * DK];
__device__ float    g_v[B_ * H_ * S_ * DK];
__device__ float    g_ctx[B_ * S_ * INNER_];     // fp32 [B,S,H*DK]
__device__ float    g_bias[H_ * NREL];
// int8 2-slice quantized operands for QKV projections
__device__ unsigned g_x8H[4096 * 256], g_x8L[4096 * 256];   // [row][kword]
__device__ unsigned g_w8H[3 * 1024 * 256], g_w8L[3 * 1024 * 256]; // [z][col][kword]
__device__ float    g_sx[4096];                  // per-row scale of X
__device__ float    g_sw[3 * 1024];              // per-col scale of W

// ---------------- bf16 helpers (flash + wo GEMM) ----------------
__device__ __forceinline__ unsigned packbf(float x0, float x1) {
    __nv_bfloat162 t = __floats2bfloat162_rn(x0, x1);
    return *reinterpret_cast<unsigned*>(&t);
}
__device__ __forceinline__ void split2(float x0, float x1,
                                       unsigned& h, unsigned& l) {
    float h0 = __bfloat162float(__float2bfloat16_rn(x0));
    float h1 = __bfloat162float(__float2bfloat16_rn(x1));
    h = packbf(h0, h1);
    l = packbf(x0 - h0, x1 - h1);
}
__device__ __forceinline__ void mma_bf16(float* c, unsigned a0, unsigned a1,
                                         unsigned a2, unsigned a3,
                                         unsigned b0, unsigned b1) {
    asm volatile(
        "mma.sync.aligned.m16n8k16.row.col.f32.bf16.bf16.f32 "
        "{%0,%1,%2,%3}, {%4,%5,%6,%7}, {%8,%9}, {%0,%1,%2,%3};\n"
        : "+f"(c[0]), "+f"(c[1]), "+f"(c[2]), "+f"(c[3])
        : "r"(a0), "r"(a1), "r"(a2), "r"(a3), "r"(b0), "r"(b1));
}
__device__ __forceinline__ void mma3(float* c, const unsigned* aH,
                                     const unsigned* aL, unsigned bH0,
                                     unsigned bH1, unsigned bL0, unsigned bL1) {
    mma_bf16(c, aH[0], aH[1], aH[2], aH[3], bH0, bH1);
    mma_bf16(c, aH[0], aH[1], aH[2], aH[3], bL0, bL1);
    mma_bf16(c, aL[0], aL[1], aL[2], aL[3], bH0, bH1);
}
// int8 mma, k32
__device__ __forceinline__ void mma_s8(int* c, unsigned a0, unsigned a1,
                                       unsigned a2, unsigned a3,
                                       unsigned b0, unsigned b1) {
    asm volatile(
        "mma.sync.aligned.m16n8k32.row.col.s32.s8.s8.s32 "
        "{%0,%1,%2,%3}, {%4,%5,%6,%7}, {%8,%9}, {%0,%1,%2,%3};\n"
        : "+r"(c[0]), "+r"(c[1]), "+r"(c[2]), "+r"(c[3])
        : "r"(a0), "r"(a1), "r"(a2), "r"(a3), "r"(b0), "r"(b1));
}

// quantize one value: q = x*16256/s, hi = round(q/128) in [-127,127], lo = q-128hi
__device__ __forceinline__ void quant2(float x, float inv, int& hi, int& lo) {
    float q = x * inv;
    hi = __float2int_rn(q * 0.0078125f);      // /128
    hi = max(-127, min(127, hi));
    lo = __float2int_rn(q - 128.0f * (float)hi);
    lo = max(-127, min(127, lo));
}
__device__ __forceinline__ unsigned pack4(int b0, int b1, int b2, int b3) {
    return (unsigned)(uint8_t)b0 | ((unsigned)(uint8_t)b1 << 8) |
           ((unsigned)(uint8_t)b2 << 16) | ((unsigned)(uint8_t)b3 << 24);
}

// ---------------- relative position bias table ----------------
__global__ void bias_kernel(const float* __restrict__ table) {
    int idx = blockIdx.x * blockDim.x + threadIdx.x;
    if (idx >= H_ * NREL) return;
    int h   = idx / NREL;
    int rel = (idx % NREL) - 2047;
    int rb  = (rel > 0) ? 16 : 0;
    int r   = abs(rel);
    int v;
    if (r < 8) {
        v = r;
    } else {
        float t = logf((float)r * 0.125f) / 2.7725887f * 8.0f;
        v = 8 + (int)t;
        v = min(v, 15);
    }
    g_bias[idx] = table[(rb + v) * H_ + h];
}

// ---------------- quantize X: one block per row ----------------
__global__ __launch_bounds__(256) void prep_xq(const float* __restrict__ X) {
    __shared__ float red[256];
    int row = blockIdx.x, tid = threadIdx.x;
    float4 v = *(const float4*)(X + (size_t)row * 1024 + tid * 4);
    float m = fmaxf(fmaxf(fabsf(v.x), fabsf(v.y)), fmaxf(fabsf(v.z), fabsf(v.w)));
    red[tid] = m;
    __syncthreads();
    for (int s = 128; s > 0; s >>= 1) {
        if (tid < s) red[tid] = fmaxf(red[tid], red[tid + s]);
        __syncthreads();
    }
    float sc = fmaxf(red[0], 1e-20f);
    float inv = 16256.0f / sc;
    int h0, l0, h1, l1, h2, l2, h3, l3;
    quant2(v.x, inv, h0, l0);
    quant2(v.y, inv, h1, l1);
    quant2(v.z, inv, h2, l2);
    quant2(v.w, inv, h3, l3);
    g_x8H[row * 256 + tid] = pack4(h0, h1, h2, h3);
    g_x8L[row * 256 + tid] = pack4(l0, l1, l2, l3);
    if (tid == 0) g_sx[row] = sc;
}

// ---------------- quantize W (per column): block = 64 cols ----------------
__global__ __launch_bounds__(256) void prep_wq(const float* __restrict__ wq,
                                               const float* __restrict__ wk,
                                               const float* __restrict__ wv) {
    __shared__ float cm[4][64];
    __shared__ float scs[64];
    int z = blockIdx.y;
    const float* W = (z == 0) ? wq : (z == 1) ? wk : wv;
    int col0 = blockIdx.x * 64;
    int tid = threadIdx.x;
    int c = tid & 63, kk = tid >> 6;     // 4 k-lanes x 64 cols
    float m = 0.0f;
    for (int k = kk; k < 1024; k += 4)
        m = fmaxf(m, fabsf(W[(size_t)k * 1024 + col0 + c]));
    cm[kk][c] = m;
    __syncthreads();
    if (kk == 0) {
        float s = fmaxf(fmaxf(cm[0][c], cm[1][c]), fmaxf(cm[2][c], cm[3][c]));
        s = fmaxf(s, 1e-20f);
        scs[c] = s;
        g_sw[z * 1024 + col0 + c] = s;
    }
    __syncthreads();
    float inv = 16256.0f / scs[c];
    // pack: thread handles kwords w = i*4 + kk
    for (int i = 0; i < 64; i++) {
        int w = i * 4 + kk;
        int h[4], l[4];
#pragma unroll
        for (int j = 0; j < 4; j++)
            quant2(W[(size_t)(4 * w + j) * 1024 + col0 + c], inv, h[j], l[j]);
        size_t o = (size_t)z * 262144 + (size_t)(col0 + c) * 256 + w;
        g_w8H[o] = pack4(h[0], h[1], h[2], h[3]);
        g_w8L[o] = pack4(l[0], l[1], l[2], l[3]);
    }
}

// ---------------- int8 2-slice GEMM for QKV: CTA 128x64, warp 32x32 ---------
#define AP8 12   // 8 kwords + 4 pad
__global__ __launch_bounds__(256) void gemm_i8() {
    __shared__ unsigned AsH[128 * AP8], AsL[128 * AP8];
    __shared__ unsigned BsH[64 * AP8], BsL[64 * AP8];

    int z = blockIdx.z;
    int tid = threadIdx.x, warp = tid >> 5, lane = tid & 31;
    int g = lane >> 2, tig = lane & 3;
    int wm = (warp >> 1) * 32, wn = (warp & 1) * 32;
    int bx = blockIdx.x, by = blockIdx.y;

    int ar = tid >> 1, ah = tid & 1;      // A: row, word-half
    int bc = tid >> 2, bw = (tid & 3) * 2; // B: col, word-pair
    const unsigned* xH = g_x8H + (size_t)(by * 128 + ar) * 256 + ah * 4;
    const unsigned* xL = g_x8L + (size_t)(by * 128 + ar) * 256 + ah * 4;
    const unsigned* wH = g_w8H + (size_t)z * 262144 + (size_t)(bx * 64 + bc) * 256 + bw;
    const unsigned* wL = g_w8L + (size_t)z * 262144 + (size_t)(bx * 64 + bc) * 256 + bw;

    int accA[2][4][4], accB[2][4][4];
#pragma unroll
    for (int mi = 0; mi < 2; mi++)
#pragma unroll
        for (int ni = 0; ni < 4; ni++)
#pragma unroll
            for (int c = 0; c < 4; c++) { accA[mi][ni][c] = 0; accB[mi][ni][c] = 0; }

    uint4 pAH, pAL;
    uint2 pBH, pBL;
    pAH = *(const uint4*)(xH);
    pAL = *(const uint4*)(xL);
    pBH = *(const uint2*)(wH);
    pBL = *(const uint2*)(wL);

    for (int kt = 0; kt < 32; kt++) {
        *(uint4*)&AsH[ar * AP8 + ah * 4] = pAH;
        *(uint4*)&AsL[ar * AP8 + ah * 4] = pAL;
        *(uint2*)&BsH[bc * AP8 + bw] = pBH;
        *(uint2*)&BsL[bc * AP8 + bw] = pBL;
        __syncthreads();

        if (kt + 1 < 32) {
            int o = (kt + 1) * 8;
            pAH = *(const uint4*)(xH + o);
            pAL = *(const uint4*)(xL + o);
            pBH = *(const uint2*)(wH + o);
            pBL = *(const uint2*)(wL + o);
        }

        unsigned afH[2][4], afL[2][4], bfH[4][2], bfL[4][2];
#pragma unroll
        for (int mi = 0; mi < 2; mi++) {
            int r = wm + mi * 16 + g;
            afH[mi][0] = AsH[r * AP8 + tig];
            afH[mi][1] = AsH[(r + 8) * AP8 + tig];
            afH[mi][2] = AsH[r * AP8 + 4 + tig];
            afH[mi][3] = AsH[(r + 8) * AP8 + 4 + tig];
            afL[mi][0] = AsL[r * AP8 + tig];
            afL[mi][1] = AsL[(r + 8) * AP8 + tig];
            afL[mi][2] = AsL[r * AP8 + 4 + tig];
            afL[mi][3] = AsL[(r + 8) * AP8 + 4 + tig];
        }
#pragma unroll
        for (int ni = 0; ni < 4; ni++) {
            int c = wn + ni * 8 + g;
            bfH[ni][0] = BsH[c * AP8 + tig];
            bfH[ni][1] = BsH[c * AP8 + 4 + tig];
            bfL[ni][0] = BsL[c * AP8 + tig];
            bfL[ni][1] = BsL[c * AP8 + 4 + tig];
        }
#pragma unroll
        for (int mi = 0; mi < 2; mi++)
#pragma unroll
            for (int ni = 0; ni < 4; ni++) {
                mma_s8(accA[mi][ni], afH[mi][0], afH[mi][1], afH[mi][2],
                       afH[mi][3], bfH[ni][0], bfH[ni][1]);
                mma_s8(accB[mi][ni], afH[mi][0], afH[mi][1], afH[mi][2],
                       afH[mi][3], bfL[ni][0], bfL[ni][1]);
                mma_s8(accB[mi][ni], afL[mi][0], afL[mi][1], afL[mi][2],
                       afL[mi][3], bfH[ni][0], bfH[ni][1]);
            }
        __syncthreads();
    }

    // epilogue: out = sx[r] * sw[n] * (c1*HH + c2*(HL+LH))
    const float QD = 1.0f / (16256.0f * 16256.0f);
    const float c1 = 16384.0f * QD, c2 = 128.0f * QD;
    float* dst = (z == 0) ? g_q : (z == 1) ? g_k : g_v;
#pragma unroll
    for (int mi = 0; mi < 2; mi++)
#pragma unroll
        for (int ni = 0; ni < 4; ni++) {
            int r0 = by * 128 + wm + mi * 16 + g;
            int c0 = bx * 64 + wn + ni * 8 + tig * 2;
            float sw0 = g_sw[z * 1024 + c0], sw1 = g_sw[z * 1024 + c0 + 1];
            int h = c0 >> 6, d = c0 & 63;
            {
                float sx = g_sx[r0];
                int b = r0 >> 11, s = r0 & 2047;
                float o0 = sx * sw0 * (c1 * (float)accA[mi][ni][0] + c2 * (float)accB[mi][ni][0]);
                float o1 = sx * sw1 * (c1 * (float)accA[mi][ni][1] + c2 * (float)accB[mi][ni][1]);
                *(float2*)(dst + (size_t)((b * H_ + h) * S_ + s) * DK + d) =
                    make_float2(o0, o1);
            }
            {
                int r1 = r0 + 8;
                float sx = g_sx[r1];
                int b = r1 >> 11, s = r1 & 2047;
                float o0 = sx * sw0 * (c1 * (float)accA[mi][ni][2] + c2 * (float)accB[mi][ni][2]);
                float o1 = sx * sw1 * (c1 * (float)accA[mi][ni][3] + c2 * (float)accB[mi][ni][3]);
                *(float2*)(dst + (size_t)((b * H_ + h) * S_ + s) * DK + d) =
                    make_float2(o0, o1);
            }
        }
}

// ---------------- 3xBF16 GEMM 128x128x32 (wo projection, R10) ---------------
#define APITCH 20
#define BPITCH 136
#define GEMM_SMEM ((2 * 128 * APITCH + 2 * 16 * BPITCH) * 4)

__global__ __launch_bounds__(256) void gemm_wo(const float* __restrict__ W,
                                               float* __restrict__ Copt) {
    extern __shared__ unsigned smg[];
    unsigned* AsH = smg;
    unsigned* AsL = AsH + 128 * APITCH;
    unsigned* BsH = AsL + 128 * APITCH;
    unsigned* BsL = BsH + 16 * BPITCH;

    const float* A = g_ctx;
    const int K = 1024, N = 1024;
    int tid  = threadIdx.x;
    int warp = tid >> 5, lane = tid & 31;
    int g = lane >> 2, tig = lane & 3;
    int wm = (warp >> 2) * 64, wn = (warp & 3) * 32;
    int bx = blockIdx.x, by = blockIdx.y;

    float acc[4][4][4];
#pragma unroll
    for (int mi = 0; mi < 4; mi++)
#pragma unroll
        for (int ni = 0; ni < 4; ni++)
#pragma unroll
            for (int c = 0; c < 4; c++) acc[mi][ni][c] = 0.0f;

    float4 aR[4], bR[4];
#pragma unroll
    for (int i = 0; i < 4; i++) {
        int ch = tid + i * 256;
        int r = ch >> 3, cq = ch & 7;
        aR[i] = *(const float4*)(A + (size_t)(by * 128 + r) * K + cq * 4);
    }
#pragma unroll
    for (int i = 0; i < 2; i++) {
        int u = tid + i * 256;
        int p = u >> 5, cq = u & 31;
        bR[2 * i]     = *(const float4*)(W + (size_t)(2 * p) * N + bx * 128 + cq * 4);
        bR[2 * i + 1] = *(const float4*)(W + (size_t)(2 * p + 1) * N + bx * 128 + cq * 4);
    }

    for (int kt = 0; kt < 32; kt++) {
#pragma unroll
        for (int i = 0; i < 4; i++) {
            int ch = tid + i * 256;
            int r = ch >> 3, cq = ch & 7;
            uint2 h, l;
            split2(aR[i].x, aR[i].y, h.x, l.x);
            split2(aR[i].z, aR[i].w, h.y, l.y);
            *(uint2*)&AsH[r * APITCH + cq * 2] = h;
            *(uint2*)&AsL[r * APITCH + cq * 2] = l;
        }
#pragma unroll
        for (int i = 0; i < 2; i++) {
            int u = tid + i * 256;
            int p = u >> 5, cq = u & 31;
            float4 ra = bR[2 * i], rb = bR[2 * i + 1];
            uint4 h, l;
            split2(ra.x, rb.x, h.x, l.x);
            split2(ra.y, rb.y, h.y, l.y);
            split2(ra.z, rb.z, h.z, l.z);
            split2(ra.w, rb.w, h.w, l.w);
            *(uint4*)&BsH[p * BPITCH + cq * 4] = h;
            *(uint4*)&BsL[p * BPITCH + cq * 4] = l;
        }
        __syncthreads();

        if (kt + 1 < 32) {
            int k0 = (kt + 1) * 32;
#pragma unroll
            for (int i = 0; i < 4; i++) {
                int ch = tid + i * 256;
                int r = ch >> 3, cq = ch & 7;
                aR[i] = *(const float4*)(A + (size_t)(by * 128 + r) * K + k0 + cq * 4);
            }
#pragma unroll
            for (int i = 0; i < 2; i++) {
                int u = tid + i * 256;
                int p = u >> 5, cq = u & 31;
                bR[2 * i]     = *(const float4*)(W + (size_t)(k0 + 2 * p) * N + bx * 128 + cq * 4);
                bR[2 * i + 1] = *(const float4*)(W + (size_t)(k0 + 2 * p + 1) * N + bx * 128 + cq * 4);
            }
        }

#pragma unroll
        for (int ks = 0; ks < 2; ks++) {
            int kp = ks * 8;
            unsigned afH[4][4], afL[4][4], bfH[4][2], bfL[4][2];
#pragma unroll
            for (int mi = 0; mi < 4; mi++) {
                int r = wm + mi * 16 + g;
                afH[mi][0] = AsH[r * APITCH + kp + tig];
                afH[mi][1] = AsH[(r + 8) * APITCH + kp + tig];
                afH[mi][2] = AsH[r * APITCH + kp + tig + 4];
                afH[mi][3] = AsH[(r + 8) * APITCH + kp + tig + 4];
                afL[mi][0] = AsL[r * APITCH + kp + tig];
                afL[mi][1] = AsL[(r + 8) * APITCH + kp + tig];
                afL[mi][2] = AsL[r * APITCH + kp + tig + 4];
                afL[mi][3] = AsL[(r + 8) * APITCH + kp + tig + 4];
            }
#pragma unroll
            for (int ni = 0; ni < 4; ni++) {
                int c = wn + ni * 8 + g;
                bfH[ni][0] = BsH[(kp + tig) * BPITCH + c];
                bfH[ni][1] = BsH[(kp + tig + 4) * BPITCH + c];
                bfL[ni][0] = BsL[(kp + tig) * BPITCH + c];
                bfL[ni][1] = BsL[(kp + tig + 4) * BPITCH + c];
            }
#pragma unroll
            for (int mi = 0; mi < 4; mi++)
#pragma unroll
                for (int ni = 0; ni < 4; ni++)
                    mma3(acc[mi][ni], afH[mi], afL[mi], bfH[ni][0], bfH[ni][1],
                         bfL[ni][0], bfL[ni][1]);
        }
        __syncthreads();
    }

#pragma unroll
    for (int mi = 0; mi < 4; mi++)
#pragma unroll
        for (int ni = 0; ni < 4; ni++) {
            int r0 = by * 128 + wm + mi * 16 + g;
            int c0 = bx * 128 + wn + ni * 8 + tig * 2;
            *(float2*)(Copt + (size_t)r0 * N + c0) =
                make_float2(acc[mi][ni][0], acc[mi][ni][1]);
            *(float2*)(Copt + (size_t)(r0 + 8) * N + c0) =
                make_float2(acc[mi][ni][2], acc[mi][ni][3]);
        }
}

// ---------------- 3xBF16 flash attention, 128x64 tiles, 8 warps (R10) -------
#define QP 36
#define KP 36
#define VP 72
#define PP 36
#define FLASH_SMEM ((2 * 128 * QP + 2 * 64 * KP + 2 * 32 * VP + \
                     2 * 128 * PP + 192) * 4)

__global__ __launch_bounds__(256) void flash_bf16x3() {
    extern __shared__ unsigned smu[];
    unsigned* QsH = smu;
    unsigned* QsL = QsH + 128 * QP;
    unsigned* KsH = QsL + 128 * QP;
    unsigned* KsL = KsH + 64 * KP;
    unsigned* VsH = KsL + 64 * KP;
    unsigned* VsL = VsH + 32 * VP;
    unsigned* PsH = VsL + 32 * VP;
    unsigned* PsL = PsH + 128 * PP;
    float* sB = (float*)(PsL + 128 * PP);

    int qb = blockIdx.x, h = blockIdx.y, b = blockIdx.z;
    int tid  = threadIdx.x;
    int warp = tid >> 5, lane = tid & 31;
    int g = lane >> 2, tig = lane & 3;

    const float* Qg = g_q + ((size_t)(b * H_ + h) * S_ + qb * 128) * DK;
    const float* Kg = g_k + (size_t)(b * H_ + h) * S_ * DK;
    const float* Vg = g_v + (size_t)(b * H_ + h) * S_ * DK;

#pragma unroll
    for (int i = 0; i < 8; i++) {
        int ch = tid + i * 256;
        int r = ch >> 4, cq = ch & 15;
        float4 v = *(const float4*)(Qg + (size_t)r * DK + cq * 4);
        uint2 hh, ll;
        split2(v.x, v.y, hh.x, ll.x);
        split2(v.z, v.w, hh.y, ll.y);
        *(uint2*)&QsH[r * QP + cq * 2] = hh;
        *(uint2*)&QsL[r * QP + cq * 2] = ll;
    }

    float oacc[8][4];
#pragma unroll
    for (int ni = 0; ni < 8; ni++)
#pragma unroll
        for (int c = 0; c < 4; c++) oacc[ni][c] = 0.0f;
    float m_i[2] = {-1e30f, -1e30f}, l_i[2] = {0.0f, 0.0f};

    for (int kb = 0; kb < S_ / 64; kb++) {
#pragma unroll
        for (int i = 0; i < 4; i++) {
            int ch = tid + i * 256;
            int r = ch >> 4, cq = ch & 15;
            float4 kv = *(const float4*)(Kg + (size_t)(kb * 64 + r) * DK + cq * 4);
            uint2 hh, ll;
            split2(kv.x, kv.y, hh.x, ll.x);
            split2(kv.z, kv.w, hh.y, ll.y);
            *(uint2*)&KsH[r * KP + cq * 2] = hh;
            *(uint2*)&KsL[r * KP + cq * 2] = ll;
        }
#pragma unroll
        for (int i = 0; i < 2; i++) {
            int u = tid + i * 256;
            int p = u >> 4, cq = u & 15;
            float4 va = *(const float4*)(Vg + (size_t)(kb * 64 + 2 * p) * DK + cq * 4);
            float4 vb = *(const float4*)(Vg + (size_t)(kb * 64 + 2 * p + 1) * DK + cq * 4);
            uint4 hh, ll;
            split2(va.x, vb.x, hh.x, ll.x);
            split2(va.y, vb.y, hh.y, ll.y);
            split2(va.z, vb.z, hh.z, ll.z);
            split2(va.w, vb.w, hh.w, ll.w);
            *(uint4*)&VsH[p * VP + cq * 4] = hh;
            *(uint4*)&VsL[p * VP + cq * 4] = ll;
        }
        if (tid < 191)
            sB[tid] = g_bias[h * NREL + (kb * 64 - qb * 128) - 127 + 2047 + tid];
        __syncthreads();

        float sacc[8][4];
#pragma unroll
        for (int ni = 0; ni < 8; ni++)
#pragma unroll
            for (int c = 0; c < 4; c++) sacc[ni][c] = 0.0f;

#pragma unroll
        for (int ks = 0; ks < 4; ks++) {
            int kp = ks * 8;
            int rq = warp * 16 + g;
            unsigned aH[4], aL[4];
            aH[0] = QsH[rq * QP + kp + tig];
            aH[1] = QsH[(rq + 8) * QP + kp + tig];
            aH[2] = QsH[rq * QP + kp + tig + 4];
            aH[3] = QsH[(rq + 8) * QP + kp + tig + 4];
            aL[0] = QsL[rq * QP + kp + tig];
            aL[1] = QsL[(rq + 8) * QP + kp + tig];
            aL[2] = QsL[rq * QP + kp + tig + 4];
            aL[3] = QsL[(rq + 8) * QP + kp + tig + 4];
#pragma unroll
            for (int ni = 0; ni < 8; ni++) {
                int rk = ni * 8 + g;
                unsigned bH0 = KsH[rk * KP + kp + tig];
                unsigned bH1 = KsH[rk * KP + kp + tig + 4];
                unsigned bL0 = KsL[rk * KP + kp + tig];
                unsigned bL1 = KsL[rk * KP + kp + tig + 4];
                mma3(sacc[ni], aH, aL, bH0, bH1, bL0, bL1);
            }
        }

#pragma unroll
        for (int rh = 0; rh < 2; rh++) {
            int qr = warp * 16 + g + 8 * rh;
            float rm = -1e30f;
#pragma unroll
            for (int ni = 0; ni < 8; ni++) {
                int kc = ni * 8 + tig * 2;
                sacc[ni][2 * rh]     += sB[kc - qr + 127];
                sacc[ni][2 * rh + 1] += sB[kc + 1 - qr + 127];
                rm = fmaxf(rm, fmaxf(sacc[ni][2 * rh], sacc[ni][2 * rh + 1]));
            }
            rm = fmaxf(rm, __shfl_xor_sync(0xffffffffu, rm, 1));
            rm = fmaxf(rm, __shfl_xor_sync(0xffffffffu, rm, 2));
            float mn   = fmaxf(m_i[rh], rm);
            float corr = __expf(m_i[rh] - mn);
            float rs = 0.0f;
#pragma unroll
            for (int ni = 0; ni < 8; ni++) {
                float p0 = __expf(sacc[ni][2 * rh] - mn);
                float p1 = __expf(sacc[ni][2 * rh + 1] - mn);
                rs += p0 + p1;
                unsigned ph, pl;
                split2(p0, p1, ph, pl);
                PsH[qr * PP + ni * 4 + tig] = ph;
                PsL[qr * PP + ni * 4 + tig] = pl;
                oacc[ni][2 * rh]     *= corr;
                oacc[ni][2 * rh + 1] *= corr;
            }
            rs += __shfl_xor_sync(0xffffffffu, rs, 1);
            rs += __shfl_xor_sync(0xffffffffu, rs, 2);
            l_i[rh] = l_i[rh] * corr + rs;
            m_i[rh] = mn;
        }
        __syncwarp();

#pragma unroll
        for (int ks = 0; ks < 4; ks++) {
            int kp = ks * 8;
            int pr = warp * 16 + g;
            unsigned aH[4], aL[4];
            aH[0] = PsH[pr * PP + kp + tig];
            aH[1] = PsH[(pr + 8) * PP + kp + tig];
            aH[2] = PsH[pr * PP + kp + tig + 4];
            aH[3] = PsH[(pr + 8) * PP + kp + tig + 4];
            aL[0] = PsL[pr * PP + kp + tig];
            aL[1] = PsL[(pr + 8) * PP + kp + tig];
            aL[2] = PsL[pr * PP + kp + tig + 4];
            aL[3] = PsL[(pr + 8) * PP + kp + tig + 4];
#pragma unroll
            for (int ni = 0; ni < 8; ni++) {
                int d = ni * 8 + g;
                unsigned bH0 = VsH[(kp + tig) * VP + d];
                unsigned bH1 = VsH[(kp + tig + 4) * VP + d];
                unsigned bL0 = VsL[(kp + tig) * VP + d];
                unsigned bL1 = VsL[(kp + tig + 4) * VP + d];
                mma3(oacc[ni], aH, aL, bH0, bH1, bL0, bL1);
            }
        }
        __syncthreads();
    }

    float inv0 = 1.0f / l_i[0], inv1 = 1.0f / l_i[1];
#pragma unroll
    for (int ni = 0; ni < 8; ni++) {
        int q0 = qb * 128 + warp * 16 + g;
        int d0 = ni * 8 + tig * 2;
        *(float2*)(g_ctx + ((size_t)b * S_ + q0) * INNER_ + h * DK + d0) =
            make_float2(oacc[ni][0] * inv0, oacc[ni][1] * inv0);
        *(float2*)(g_ctx + ((size_t)b * S_ + q0 + 8) * INNER_ + h * DK + d0) =
            make_float2(oacc[ni][2] * inv1, oacc[ni][3] * inv1);
    }
}

// ---------------- launch ----------------
extern "C" void kernel_launch(void* const* d_in, const int* in_sizes, int n_in,
                              void* d_out, int out_size) {
    const float* X     = (const float*)d_in[0];
    const float* wq    = (const float*)d_in[1];
    const float* wk    = (const float*)d_in[2];
    const float* wv    = (const float*)d_in[3];
    const float* wo    = (const float*)d_in[4];
    const float* table = (const float*)d_in[5];
    float* out = (float*)d_out;

    cudaFuncSetAttribute(gemm_wo,
                         cudaFuncAttributeMaxDynamicSharedMemorySize, GEMM_SMEM);
    cudaFuncSetAttribute(flash_bf16x3,
                         cudaFuncAttributeMaxDynamicSharedMemorySize, FLASH_SMEM);

    // 1. bias table + quantize X and QKV weights
    bias_kernel<<<(H_ * NREL + 255) / 256, 256>>>(table);
    prep_xq<<<4096, 256>>>(X);
    dim3 gpw(16, 3);
    prep_wq<<<gpw, 256>>>(wq, wk, wv);

    // 2. QKV projections on int8 tensor cores
    dim3 gq(INNER_ / 64, (B_ * S_) / 128, 3);
    gemm_i8<<<gq, 256>>>();

    // 3. flash attention (R10, unchanged)
    dim3 ga(S_ / 128, H_, B_);
    flash_bf16x3<<<ga, 256, FLASH_SMEM>>>();

    // 4. output projection (R10 bf16x3, unchanged)
    dim3 go(DM / 128, (B_ * S_) / 128);
    gemm_wo<<<go, 256, GEMM_SMEM>>>(wo, out);
}